// round 15
// baseline (speedup 1.0000x reference)
#include <cuda_runtime.h>
#include <cuda_fp16.h>
#include <cstdint>

namespace {
constexpr int B = 4, H = 16, S = 2048, D = 64;
constexpr int TQ = 128, TK = 64, NKT = S / TK;
constexpr float QSCALE = 0.18033688011112042f;   // (1/8) * log2(e): exp -> 2^x
constexpr int PIT = 72;                          // smem pitch (halves); 144B rows
constexpr int OFF_QH = 0;                        // [128][72]
constexpr int OFF_K  = OFF_QH + TQ * PIT;        // 2 buffers [64][72]
constexpr int OFF_V  = OFF_K + 2 * TK * PIT;
constexpr int SMEM_BYTES = (OFF_V + 2 * TK * PIT) * 2;   // 55,296 B -> occ 2
constexpr size_t NE = (size_t)B * H * S * D;     // 8.4M elements
constexpr size_t NA = (size_t)B * H * S * S;     // 268M attn elements
constexpr size_t NA_B = NA / B;                  // per-batch attn elements
}

__device__ float g_linv[B * H * S];              // 1/softmax-denominator
__device__ __half g_qh[NE];                      // Q scaled -> fp16
__device__ __half g_kh[NE], g_vh[NE];            // K, V rounded to fp16
__device__ __half g_ps[NA];                      // unnormalized P staging (fp16)

// ── PTX building blocks (baseline PTX: family-target safe) ──
__device__ __forceinline__ void ldsm4(uint32_t r[4], uint32_t a) {
    asm volatile("ldmatrix.sync.aligned.m8n8.x4.shared.b16 {%0,%1,%2,%3}, [%4];"
                 : "=r"(r[0]), "=r"(r[1]), "=r"(r[2]), "=r"(r[3]) : "r"(a));
}
__device__ __forceinline__ void ldsm4t(uint32_t r[4], uint32_t a) {
    asm volatile("ldmatrix.sync.aligned.m8n8.x4.trans.shared.b16 {%0,%1,%2,%3}, [%4];"
                 : "=r"(r[0]), "=r"(r[1]), "=r"(r[2]), "=r"(r[3]) : "r"(a));
}
__device__ __forceinline__ void mma16816(float c[4], const uint32_t a[4],
                                         uint32_t b0, uint32_t b1) {
    asm volatile("mma.sync.aligned.m16n8k16.row.col.f32.f16.f16.f32 "
                 "{%0,%1,%2,%3}, {%4,%5,%6,%7}, {%8,%9}, {%0,%1,%2,%3};"
                 : "+f"(c[0]), "+f"(c[1]), "+f"(c[2]), "+f"(c[3])
                 : "r"(a[0]), "r"(a[1]), "r"(a[2]), "r"(a[3]), "r"(b0), "r"(b1));
}
__device__ __forceinline__ uint32_t smem_u32(const void* p) {
    uint32_t a;
    asm("{ .reg .u64 t; cvta.to.shared.u64 t, %1; cvt.u32.u64 %0, t; }" : "=r"(a) : "l"(p));
    return a;
}
__device__ __forceinline__ void cpasync16(uint32_t dst, const void* src) {
    asm volatile("cp.async.cg.shared.global [%0], [%1], 16;" :: "r"(dst), "l"(src) : "memory");
}
#define CP_COMMIT() asm volatile("cp.async.commit_group;" ::: "memory")
#define CP_WAIT1()  asm volatile("cp.async.wait_group 1;" ::: "memory")

__device__ __forceinline__ float ex2f(float x) {
    float r; asm("ex2.approx.ftz.f32 %0, %1;" : "=f"(r) : "f"(x)); return r;
}
__device__ __forceinline__ uint32_t pack2(float a, float b) {
    __half2 h = __floats2half2_rn(a, b);
    return *reinterpret_cast<uint32_t*>(&h);
}

// ── pre-convert: q (scaled) / k / v -> fp16 scratch (~20us, DRAM-bound) ──
__global__ __launch_bounds__(256)
void preconv(const float4* __restrict__ q, const float4* __restrict__ k,
             const float4* __restrict__ v)
{
    size_t i = (size_t)blockIdx.x * 256 + threadIdx.x;
    float4 x = q[i];
    ((uint32_t*)g_qh)[2*i]   = pack2(x.x * QSCALE, x.y * QSCALE);
    ((uint32_t*)g_qh)[2*i+1] = pack2(x.z * QSCALE, x.w * QSCALE);
    x = k[i];
    ((uint32_t*)g_kh)[2*i]   = pack2(x.x, x.y); ((uint32_t*)g_kh)[2*i+1] = pack2(x.z, x.w);
    x = v[i];
    ((uint32_t*)g_vh)[2*i]   = pack2(x.x, x.y); ((uint32_t*)g_vh)[2*i+1] = pack2(x.z, x.w);
}

// ── attn_mma for ONE batch b: S=QK, exp, stage fp16 P, PV -> O, record 1/l ──
__global__ __launch_bounds__(256, 2)
void attn_mma(const int* __restrict__ mask, float* __restrict__ out, int b)
{
    extern __shared__ __half sm[];
    const uint32_t sbase = smem_u32(sm);
    const int tid = threadIdx.x;
    const int wid = tid >> 5, ln = tid & 31;
    const int g = ln >> 2, tg = ln & 3;
    const int qr = wid * 16;
    const int h = blockIdx.x, qt = blockIdx.y;
    const int bh = b * H + h;
    const int li = ln & 7, s1 = (ln >> 3) & 1, s2 = ln >> 4;

    auto issue_kv = [&](int kt, int buf) {
        const __half* kg = g_kh + ((size_t)bh * S + (size_t)kt * TK) * D;
        const __half* vg = g_vh + ((size_t)bh * S + (size_t)kt * TK) * D;
        #pragma unroll
        for (int i = 0; i < 2; i++) {
            int f = tid + i * 256;
            int row = f >> 3, ch = f & 7;
            cpasync16(sbase + (uint32_t)((OFF_K + buf * TK * PIT + row * PIT) * 2) + ch * 16,
                      kg + row * 64 + ch * 8);
            cpasync16(sbase + (uint32_t)((OFF_V + buf * TK * PIT + row * PIT) * 2) + ch * 16,
                      vg + row * 64 + ch * 8);
        }
    };
    {
        const __half* qg = g_qh + ((size_t)bh * S + (size_t)qt * TQ) * D;
        #pragma unroll
        for (int i = 0; i < 4; i++) {
            int f = tid + i * 256;
            int row = f >> 3, ch = f & 7;
            cpasync16(sbase + (uint32_t)((OFF_QH + row * PIT) * 2) + ch * 16,
                      qg + row * 64 + ch * 8);
        }
    }
    issue_kv(0, 0); CP_COMMIT();
    issue_kv(1, 1); CP_COMMIT();
    CP_WAIT1();
    __syncthreads();

    uint32_t qh[4][4];
    {
        uint32_t ro = (uint32_t)((qr + li + 8 * s1) * PIT + 8 * s2) * 2;
        #pragma unroll
        for (int ks = 0; ks < 4; ks++)
            ldsm4(qh[ks], sbase + (uint32_t)OFF_QH * 2 + ro + 32 * ks);
    }

    float oacc[8][4];
    #pragma unroll
    for (int nt = 0; nt < 8; nt++)
        #pragma unroll
        for (int i = 0; i < 4; i++) oacc[nt][i] = 0.f;
    float lsum0 = 0.f, lsum1 = 0.f;

    const int* mrow = mask + (size_t)b * S * S + (size_t)(qt * TQ + qr + g) * S;
    __half*    prow = g_ps + ((size_t)bh * S + (size_t)(qt * TQ + qr + g)) * S;

    const uint32_t koff = (uint32_t)(li * PIT + 8 * s1 + 16 * s2) * 2;
    const uint32_t voff = (uint32_t)((li + 8 * s1) * PIT + 8 * s2) * 2;

    for (int kt = 0; kt < NKT; kt++) {
        const uint32_t cb = (uint32_t)((kt & 1) * TK * PIT) * 2;
        CP_WAIT1();
        __syncthreads();

        int2 m0r[8], m1r[8];
        #pragma unroll
        for (int nt = 0; nt < 8; nt++) {
            int c = kt * TK + nt * 8 + 2 * tg;
            m0r[nt] = *(const int2*)&mrow[c];
            m1r[nt] = *(const int2*)&mrow[(size_t)8 * S + c];
        }

        // ── S = Qh*Kh ──
        float sacc[8][4];
        #pragma unroll
        for (int nt = 0; nt < 8; nt++) {
            #pragma unroll
            for (int i = 0; i < 4; i++) sacc[nt][i] = 0.f;
            uint32_t ka = sbase + (uint32_t)OFF_K * 2 + cb + koff + (uint32_t)(8 * nt * PIT) * 2;
            uint32_t kh0[4], kh1[4];
            ldsm4(kh0, ka);
            ldsm4(kh1, ka + 64);
            mma16816(sacc[nt], qh[0], kh0[0], kh0[1]);
            mma16816(sacc[nt], qh[1], kh0[2], kh0[3]);
            mma16816(sacc[nt], qh[2], kh1[0], kh1[1]);
            mma16816(sacc[nt], qh[3], kh1[2], kh1[3]);
        }

        // ── mask, 2^s, pack fp16 (shared by staged STG + PV A-frags) ──
        uint32_t pp[8][2];
        #pragma unroll
        for (int nt = 0; nt < 8; nt++) {
            int c = kt * TK + nt * 8 + 2 * tg;
            float p0 = m0r[nt].x ? ex2f(sacc[nt][0]) : 0.f;
            float p1 = m0r[nt].y ? ex2f(sacc[nt][1]) : 0.f;
            float p2 = m1r[nt].x ? ex2f(sacc[nt][2]) : 0.f;
            float p3 = m1r[nt].y ? ex2f(sacc[nt][3]) : 0.f;
            lsum0 += p0 + p1; lsum1 += p2 + p3;
            pp[nt][0] = pack2(p0, p1);
            pp[nt][1] = pack2(p2, p3);
            *(uint32_t*)&prow[c]                 = pp[nt][0];
            *(uint32_t*)&prow[(size_t)8 * S + c] = pp[nt][1];
        }

        // ── O += Ph*Vh ──
        #pragma unroll
        for (int ks = 0; ks < 4; ks++) {
            uint32_t ph[4] = { pp[2*ks][0], pp[2*ks][1], pp[2*ks+1][0], pp[2*ks+1][1] };
            uint32_t va = sbase + (uint32_t)OFF_V * 2 + cb + voff + (uint32_t)(16 * ks * PIT) * 2;
            #pragma unroll
            for (int np = 0; np < 4; np++) {
                uint32_t vh[4];
                ldsm4t(vh, va + 32 * np);
                mma16816(oacc[2*np  ], ph, vh[0], vh[1]);
                mma16816(oacc[2*np+1], ph, vh[2], vh[3]);
            }
        }

        __syncthreads();
        if (kt + 2 < NKT) issue_kv(kt + 2, kt & 1);
        CP_COMMIT();
    }

    // ── reduce row sums; write O; record 1/l ──
    lsum0 += __shfl_xor_sync(0xffffffffu, lsum0, 1);
    lsum0 += __shfl_xor_sync(0xffffffffu, lsum0, 2);
    lsum1 += __shfl_xor_sync(0xffffffffu, lsum1, 1);
    lsum1 += __shfl_xor_sync(0xffffffffu, lsum1, 2);
    float inv0 = 1.0f / lsum0, inv1 = 1.0f / lsum1;

    const size_t gr0 = (size_t)bh * S + (size_t)(qt * TQ + qr + g);
    float* or0 = out + gr0 * D;
    float* or1 = out + (gr0 + 8) * D;
    #pragma unroll
    for (int nt = 0; nt < 8; nt++) {
        int c = nt * 8 + 2 * tg;
        *(float2*)&or0[c] = make_float2(oacc[nt][0] * inv0, oacc[nt][1] * inv0);
        *(float2*)&or1[c] = make_float2(oacc[nt][2] * inv1, oacc[nt][3] * inv1);
    }
    if (tg == 0) { g_linv[gr0] = inv0; g_linv[gr0 + 8] = inv1; }
}

// attn[row,:] = fp16_staged[row,:] * (1/l[row]); one batch-chunk per launch
__global__ __launch_bounds__(256)
void attn_rescale(float* __restrict__ attn, unsigned long long base4)
{
    size_t i = (size_t)base4 + (size_t)blockIdx.x * 256 + threadIdx.x;  // float4 idx
    float inv = g_linv[i >> 9];                          // S/4 = 512 float4 per row
    uint2 u = ((const uint2*)g_ps)[i];
    __half2 h0 = *(__half2*)&u.x, h1 = *(__half2*)&u.y;
    float2 f0 = __half22float2(h0), f1 = __half22float2(h1);
    ((float4*)attn)[i] = make_float4(f0.x * inv, f0.y * inv, f1.x * inv, f1.y * inv);
}

// ── persistent side stream + events (host-side objects; created at program
//    init, NOT per-call; no device memory allocation involved) ──
namespace {
struct SideStream {
    cudaStream_t s2 = nullptr;
    cudaEvent_t  ev[B + 1] = {};
    bool ok = false;
    SideStream() {
        ok = (cudaStreamCreateWithFlags(&s2, cudaStreamNonBlocking) == cudaSuccess);
        for (int i = 0; ok && i <= B; i++)
            ok = (cudaEventCreateWithFlags(&ev[i], cudaEventDisableTiming) == cudaSuccess);
    }
};
SideStream g_ss;
}

extern "C" void kernel_launch(void* const* d_in, const int* in_sizes, int n_in,
                              void* d_out, int out_size)
{
    const float* q    = (const float*)d_in[0];
    const float* k    = (const float*)d_in[1];
    const float* v    = (const float*)d_in[2];
    const int*   mask = (const int*)d_in[3];
    float* out  = (float*)d_out;
    float* attn = out + (size_t)B * H * S * D;           // tuple: (output, attn)

    cudaFuncSetAttribute(attn_mma, cudaFuncAttributeMaxDynamicSharedMemorySize, SMEM_BYTES);

    preconv<<<(unsigned)(NE / 4 / 256), 256>>>((const float4*)q, (const float4*)k,
                                               (const float4*)v);

    dim3 grid(H, S / TQ);                                 // 256 CTAs per batch chunk
    const unsigned rblocks = (unsigned)(NA_B / 4 / 256);  // rescale blocks per chunk

    if (g_ss.ok) {
        // pipelined: rescale(b) on side stream overlaps attn_mma(b+1) on main
        for (int b = 0; b < B; b++) {
            attn_mma<<<grid, 256, SMEM_BYTES>>>(mask, out, b);
            cudaEventRecord(g_ss.ev[b], 0);
            cudaStreamWaitEvent(g_ss.s2, g_ss.ev[b], 0);
            attn_rescale<<<rblocks, 256, 0, g_ss.s2>>>(attn,
                (unsigned long long)((size_t)b * NA_B / 4));
        }
        cudaEventRecord(g_ss.ev[B], g_ss.s2);             // join side stream back
        cudaStreamWaitEvent(0, g_ss.ev[B], 0);
    } else {
        // fallback: serialized schedule (identical to the 746us champion)
        for (int b = 0; b < B; b++)
            attn_mma<<<grid, 256, SMEM_BYTES>>>(mask, out, b);
        attn_rescale<<<(unsigned)(NA / 4 / 256), 256>>>(attn, 0ull);
    }
}

// round 16
// speedup vs baseline: 1.8880x; 1.8880x over previous
#include <cuda_runtime.h>
#include <cuda_fp16.h>
#include <cstdint>

namespace {
constexpr int B = 4, H = 16, S = 2048, D = 64;
constexpr int TQ = 128, TK = 64, NKT = S / TK;
constexpr float QSCALE = 0.18033688011112042f;   // (1/8) * log2(e): exp -> 2^x
constexpr int PIT = 72;                          // K/V/Q smem pitch (halves); 144B
constexpr int OFF_QH = 0;                        // [128][72]
constexpr int OFF_K  = OFF_QH + TQ * PIT;        // 2 buffers [64][72]
constexpr int OFF_V  = OFF_K + 2 * TK * PIT;
constexpr int OFF_PS = OFF_V + 2 * TK * PIT;     // P stage [128][72] (pitch 144B, 16B-aligned rows)
constexpr int SMEM_BYTES = (OFF_PS + TQ * PIT) * 2;      // 73,728 B -> occ 2
constexpr size_t NE = (size_t)B * H * S * D;     // 8.4M elements
constexpr size_t NA = (size_t)B * H * S * S;     // 268M attn elements
}

__device__ float g_linv[B * H * S];              // 1/softmax-denominator
__device__ __half g_qh[NE];                      // Q scaled -> fp16
__device__ __half g_kh[NE], g_vh[NE];            // K, V rounded to fp16
__device__ __half g_ps[NA];                      // unnormalized P staging (fp16)
__device__ uint32_t g_mb[(size_t)B * S * S / 32];// bit-packed mask (2MB, L2-resident)

// ── PTX building blocks (baseline PTX: family-target safe) ──
__device__ __forceinline__ void ldsm4(uint32_t r[4], uint32_t a) {
    asm volatile("ldmatrix.sync.aligned.m8n8.x4.shared.b16 {%0,%1,%2,%3}, [%4];"
                 : "=r"(r[0]), "=r"(r[1]), "=r"(r[2]), "=r"(r[3]) : "r"(a));
}
__device__ __forceinline__ void ldsm4t(uint32_t r[4], uint32_t a) {
    asm volatile("ldmatrix.sync.aligned.m8n8.x4.trans.shared.b16 {%0,%1,%2,%3}, [%4];"
                 : "=r"(r[0]), "=r"(r[1]), "=r"(r[2]), "=r"(r[3]) : "r"(a));
}
__device__ __forceinline__ void mma16816(float c[4], const uint32_t a[4],
                                         uint32_t b0, uint32_t b1) {
    asm volatile("mma.sync.aligned.m16n8k16.row.col.f32.f16.f16.f32 "
                 "{%0,%1,%2,%3}, {%4,%5,%6,%7}, {%8,%9}, {%0,%1,%2,%3};"
                 : "+f"(c[0]), "+f"(c[1]), "+f"(c[2]), "+f"(c[3])
                 : "r"(a[0]), "r"(a[1]), "r"(a[2]), "r"(a[3]), "r"(b0), "r"(b1));
}
__device__ __forceinline__ uint32_t smem_u32(const void* p) {
    uint32_t a;
    asm("{ .reg .u64 t; cvta.to.shared.u64 t, %1; cvt.u32.u64 %0, t; }" : "=r"(a) : "l"(p));
    return a;
}
__device__ __forceinline__ void cpasync16(uint32_t dst, const void* src) {
    asm volatile("cp.async.cg.shared.global [%0], [%1], 16;" :: "r"(dst), "l"(src) : "memory");
}
#define CP_COMMIT() asm volatile("cp.async.commit_group;" ::: "memory")
#define CP_WAIT1()  asm volatile("cp.async.wait_group 1;" ::: "memory")

__device__ __forceinline__ float ex2f(float x) {
    float r; asm("ex2.approx.ftz.f32 %0, %1;" : "=f"(r) : "f"(x)); return r;
}
__device__ __forceinline__ uint32_t pack2(float a, float b) {
    __half2 h = __floats2half2_rn(a, b);
    return *reinterpret_cast<uint32_t*>(&h);
}

// ── pre-convert: q (scaled) / k / v -> fp16 scratch (~20us, DRAM-bound) ──
__global__ __launch_bounds__(256)
void preconv(const float4* __restrict__ q, const float4* __restrict__ k,
             const float4* __restrict__ v)
{
    size_t i = (size_t)blockIdx.x * 256 + threadIdx.x;
    float4 x = q[i];
    ((uint32_t*)g_qh)[2*i]   = pack2(x.x * QSCALE, x.y * QSCALE);
    ((uint32_t*)g_qh)[2*i+1] = pack2(x.z * QSCALE, x.w * QSCALE);
    x = k[i];
    ((uint32_t*)g_kh)[2*i]   = pack2(x.x, x.y); ((uint32_t*)g_kh)[2*i+1] = pack2(x.z, x.w);
    x = v[i];
    ((uint32_t*)g_vh)[2*i]   = pack2(x.x, x.y); ((uint32_t*)g_vh)[2*i+1] = pack2(x.z, x.w);
}

// ── pack mask to bits: 67MB int32 -> 2MB bitfield (~10us, DRAM-bound) ──
__global__ __launch_bounds__(256)
void maskpack(const int* __restrict__ mask)
{
    size_t i = (size_t)blockIdx.x * 256 + threadIdx.x;
    uint32_t w = __ballot_sync(0xffffffffu, mask[i] != 0);
    if ((threadIdx.x & 31) == 0) g_mb[i >> 5] = w;
}

__global__ __launch_bounds__(256, 2)
void attn_mma(float* __restrict__ out)
{
    extern __shared__ __half sm[];
    const uint32_t sbase = smem_u32(sm);
    const int tid = threadIdx.x;
    const int wid = tid >> 5, ln = tid & 31;
    const int g = ln >> 2, tg = ln & 3;
    const int qr = wid * 16;
    const int h = blockIdx.x, qt = blockIdx.y, b = blockIdx.z;
    const int bh = b * H + h;
    const int li = ln & 7, s1 = (ln >> 3) & 1, s2 = ln >> 4;

    // ── async prologue: Q tile + K/V(0), K/V(1) ──
    auto issue_kv = [&](int kt, int buf) {
        const __half* kg = g_kh + ((size_t)bh * S + (size_t)kt * TK) * D;
        const __half* vg = g_vh + ((size_t)bh * S + (size_t)kt * TK) * D;
        #pragma unroll
        for (int i = 0; i < 2; i++) {
            int f = tid + i * 256;
            int row = f >> 3, ch = f & 7;
            cpasync16(sbase + (uint32_t)((OFF_K + buf * TK * PIT + row * PIT) * 2) + ch * 16,
                      kg + row * 64 + ch * 8);
            cpasync16(sbase + (uint32_t)((OFF_V + buf * TK * PIT + row * PIT) * 2) + ch * 16,
                      vg + row * 64 + ch * 8);
        }
    };
    {
        const __half* qg = g_qh + ((size_t)bh * S + (size_t)qt * TQ) * D;
        #pragma unroll
        for (int i = 0; i < 4; i++) {
            int f = tid + i * 256;
            int row = f >> 3, ch = f & 7;
            cpasync16(sbase + (uint32_t)((OFF_QH + row * PIT) * 2) + ch * 16,
                      qg + row * 64 + ch * 8);
        }
    }
    issue_kv(0, 0); CP_COMMIT();
    issue_kv(1, 1); CP_COMMIT();
    CP_WAIT1();
    __syncthreads();

    // ── Q A-fragments (registers, whole loop) ──
    uint32_t qh[4][4];
    {
        uint32_t ro = (uint32_t)((qr + li + 8 * s1) * PIT + 8 * s2) * 2;
        #pragma unroll
        for (int ks = 0; ks < 4; ks++)
            ldsm4(qh[ks], sbase + (uint32_t)OFF_QH * 2 + ro + 32 * ks);
    }

    float oacc[8][4];
    #pragma unroll
    for (int nt = 0; nt < 8; nt++)
        #pragma unroll
        for (int i = 0; i < 4; i++) oacc[nt][i] = 0.f;
    float lsum0 = 0.f, lsum1 = 0.f;

    // bit-packed mask rows (64 words per row)
    const uint2* mw0p = (const uint2*)(g_mb + ((size_t)b * S + qt * TQ + qr + g) * 64);
    const uint2* mw1p = (const uint2*)(g_mb + ((size_t)b * S + qt * TQ + qr + g + 8) * 64);
    __half* pbase = g_ps + ((size_t)bh * S + (size_t)qt * TQ) * S;

    const uint32_t koff = (uint32_t)(li * PIT + 8 * s1 + 16 * s2) * 2;
    const uint32_t voff = (uint32_t)((li + 8 * s1) * PIT + 8 * s2) * 2;
    const int prl = ln >> 3;                 // 0..3: row-in-group for STG pass
    const int pc  = ln & 7;                  // 16B chunk within 128B row

    for (int kt = 0; kt < NKT; kt++) {
        const uint32_t cb = (uint32_t)((kt & 1) * TK * PIT) * 2;
        CP_WAIT1();
        __syncthreads();

        // 2 x LDG.64: mask bits for this thread's two rows, 64 cols
        uint2 mw0 = mw0p[kt];
        uint2 mw1 = mw1p[kt];

        // ── S = Qh*Kh ──
        float sacc[8][4];
        #pragma unroll
        for (int nt = 0; nt < 8; nt++) {
            #pragma unroll
            for (int i = 0; i < 4; i++) sacc[nt][i] = 0.f;
            uint32_t ka = sbase + (uint32_t)OFF_K * 2 + cb + koff + (uint32_t)(8 * nt * PIT) * 2;
            uint32_t kh0[4], kh1[4];
            ldsm4(kh0, ka);
            ldsm4(kh1, ka + 64);
            mma16816(sacc[nt], qh[0], kh0[0], kh0[1]);
            mma16816(sacc[nt], qh[1], kh0[2], kh0[3]);
            mma16816(sacc[nt], qh[2], kh1[0], kh1[1]);
            mma16816(sacc[nt], qh[3], kh1[2], kh1[3]);
        }

        // ── mask bits, 2^s, pack fp16; STS into warp-private stage tile ──
        uint32_t pp[8][2];
        #pragma unroll
        for (int nt = 0; nt < 8; nt++) {
            uint32_t wa = (nt < 4) ? mw0.x : mw0.y;
            uint32_t wb = (nt < 4) ? mw1.x : mw1.y;
            int sh = ((nt & 3) << 3) + 2 * tg;
            float p0 = ((wa >> sh) & 1u) ? ex2f(sacc[nt][0]) : 0.f;
            float p1 = ((wa >> sh) & 2u) ? ex2f(sacc[nt][1]) : 0.f;
            float p2 = ((wb >> sh) & 1u) ? ex2f(sacc[nt][2]) : 0.f;
            float p3 = ((wb >> sh) & 2u) ? ex2f(sacc[nt][3]) : 0.f;
            lsum0 += p0 + p1; lsum1 += p2 + p3;
            pp[nt][0] = pack2(p0, p1);
            pp[nt][1] = pack2(p2, p3);
            *(uint32_t*)&sm[OFF_PS + (qr + g) * PIT + nt * 8 + 2 * tg]     = pp[nt][0];
            *(uint32_t*)&sm[OFF_PS + (qr + g + 8) * PIT + nt * 8 + 2 * tg] = pp[nt][1];
        }

        // ── O += Ph*Vh (A-frags straight from pp; overlaps STS drain) ──
        #pragma unroll
        for (int ks = 0; ks < 4; ks++) {
            uint32_t ph[4] = { pp[2*ks][0], pp[2*ks][1], pp[2*ks+1][0], pp[2*ks+1][1] };
            uint32_t va = sbase + (uint32_t)OFF_V * 2 + cb + voff + (uint32_t)(16 * ks * PIT) * 2;
            #pragma unroll
            for (int np = 0; np < 4; np++) {
                uint32_t vh[4];
                ldsm4t(vh, va + 32 * np);
                mma16816(oacc[2*np  ], ph, vh[0], vh[1]);
                mma16816(oacc[2*np+1], ph, vh[2], vh[3]);
            }
        }

        // ── warp-private transpose -> coalesced STG.128 (4 x 512B/warp) ──
        __syncwarp();
        #pragma unroll
        for (int p = 0; p < 4; p++) {
            int row_l = qr + p * 4 + prl;
            uint4 val = *(const uint4*)&sm[OFF_PS + row_l * PIT + pc * 8];
            *(uint4*)&pbase[(size_t)row_l * S + kt * TK + pc * 8] = val;
        }

        __syncthreads();
        if (kt + 2 < NKT) issue_kv(kt + 2, kt & 1);
        CP_COMMIT();
    }

    // ── reduce row sums; write O; record 1/l ──
    lsum0 += __shfl_xor_sync(0xffffffffu, lsum0, 1);
    lsum0 += __shfl_xor_sync(0xffffffffu, lsum0, 2);
    lsum1 += __shfl_xor_sync(0xffffffffu, lsum1, 1);
    lsum1 += __shfl_xor_sync(0xffffffffu, lsum1, 2);
    float inv0 = 1.0f / lsum0, inv1 = 1.0f / lsum1;

    const size_t gr0 = (size_t)bh * S + (size_t)(qt * TQ + qr + g);
    float* or0 = out + gr0 * D;
    float* or1 = out + (gr0 + 8) * D;
    #pragma unroll
    for (int nt = 0; nt < 8; nt++) {
        int c = nt * 8 + 2 * tg;
        *(float2*)&or0[c] = make_float2(oacc[nt][0] * inv0, oacc[nt][1] * inv0);
        *(float2*)&or1[c] = make_float2(oacc[nt][2] * inv1, oacc[nt][3] * inv1);
    }
    if (tg == 0) { g_linv[gr0] = inv0; g_linv[gr0 + 8] = inv1; }
}

// attn[row,:] = fp16_staged[row,:] * (1/l[row]) — reads 0.54GB, writes 1.07GB
__global__ __launch_bounds__(256)
void attn_rescale(float* __restrict__ attn)
{
    size_t i = (size_t)blockIdx.x * 256 + threadIdx.x;   // float4 index
    float inv = g_linv[i >> 9];                          // S/4 = 512 float4 per row
    uint2 u = ((const uint2*)g_ps)[i];
    __half2 h0 = *(__half2*)&u.x, h1 = *(__half2*)&u.y;
    float2 f0 = __half22float2(h0), f1 = __half22float2(h1);
    ((float4*)attn)[i] = make_float4(f0.x * inv, f0.y * inv, f1.x * inv, f1.y * inv);
}

extern "C" void kernel_launch(void* const* d_in, const int* in_sizes, int n_in,
                              void* d_out, int out_size)
{
    const float* q    = (const float*)d_in[0];
    const float* k    = (const float*)d_in[1];
    const float* v    = (const float*)d_in[2];
    const int*   mask = (const int*)d_in[3];
    float* out  = (float*)d_out;
    float* attn = out + (size_t)B * H * S * D;           // tuple: (output, attn)

    cudaFuncSetAttribute(attn_mma, cudaFuncAttributeMaxDynamicSharedMemorySize, SMEM_BYTES);

    preconv<<<(unsigned)(NE / 4 / 256), 256>>>((const float4*)q, (const float4*)k,
                                               (const float4*)v);
    maskpack<<<(unsigned)((size_t)B * S * S / 256), 256>>>(mask);

    // h fastest: concurrent CTAs share K/V and mask bits in L2
    dim3 grid(H, S / TQ, B);
    attn_mma<<<grid, 256, SMEM_BYTES>>>(out);

    attn_rescale<<<(unsigned)(NA / 4 / 256), 256>>>(attn);
}